// round 3
// baseline (speedup 1.0000x reference)
#include <cuda_runtime.h>
#include <cstdint>
#include <math.h>

// Problem constants (GRUWorldModel): OBS=128, ACT=32, H=512, B=32, N=64
#define Bq   32
#define Nq   64
#define HD   512
#define OBS  128
#define ACTD 32
#define IND  160
#define DD   128

typedef unsigned long long u64;

// ---- packed f32x2 helpers (sm_100+) ----
__device__ __forceinline__ u64 pack2(float x) {
    u64 r; asm("mov.b64 %0, {%1,%2};" : "=l"(r) : "f"(x), "f"(x)); return r;
}
__device__ __forceinline__ void fma2(u64 &d, u64 a, u64 b) {
    asm("fma.rn.f32x2 %0, %1, %2, %0;" : "+l"(d) : "l"(a), "l"(b));
}
__device__ __forceinline__ float2 unpack2(u64 v) {
    float2 f; asm("mov.b64 {%0,%1}, %2;" : "=f"(f.x), "=f"(f.y) : "l"(v)); return f;
}
__device__ __forceinline__ float sigmoidf_(float x) { return 1.0f / (1.0f + expf(-x)); }

// ============================================================================
// Per-timestep kernel: fused GEMM ( [x_t, h_{t-1}] @ [W_ih | W_hh]^T ) + gates.
// Grid: (32 b-tiles, 8 j-groups of 64). Block 256 threads.
// Tile: BM=64 rows (one b, n=0..63), BN=192 cols = {r,z,n} gate rows at the
// same j-slice, BK=16. Each thread: 8 rows x 6 cols as 8x3 f32x2 accumulators.
// Separate accumulators for the x-part and h-part of the n gate.
// h_t is written directly into the hs region of d_out; h_{t-1} is read there.
// ============================================================================
__global__ __launch_bounds__(256, 2)
void gru_step_kernel(const float* __restrict__ obs, const float* __restrict__ act,
                     const float* __restrict__ w_ih, const float* __restrict__ w_hh,
                     const float* __restrict__ b_ih, const float* __restrict__ b_hh,
                     float* __restrict__ hs, int t, int HOR, int T)
{
    const int tid = threadIdx.x;
    const int b   = blockIdx.x;        // 0..31
    const int j0  = blockIdx.y * 64;   // 0..448
    const int tym = tid >> 5;          // warp id 0..7
    const int txn = tid & 31;
    const int m0  = tym * 8;

    __shared__ float As[16][68];       // A tile transposed: As[k][m]
    __shared__ float Bs[16][194];      // B tile transposed: Bs[k][col], col<192
    __shared__ float bih_s[192];
    __shared__ float bhh_s[192];

    if (tid < 192) {
        int grow = (tid >> 6) * HD + j0 + (tid & 63);
        bih_s[tid] = b_ih[grow];
        bhh_s[tid] = b_hh[grow];
    }

    u64 accR[8], accZ[8], accHN[8], accIN[8];
    #pragma unroll
    for (int m = 0; m < 8; ++m) { accR[m] = 0; accZ[m] = 0; accHN[m] = 0; accIN[m] = 0; }

    const int am = tid >> 2;            // A-load row 0..63
    const int aq = (tid & 3) * 4;       // A-load k offset 0,4,8,12

    const bool first = (t == 0);
    const float* __restrict__ hprev_base =
        hs + ((size_t)(b * HOR + (t - 1)) * Nq) * HD;   // only deref'd if !first
    const size_t xrow = ((size_t)(b * T + t)) * Nq;

    // -------- h-phase: K = 512 over h_{t-1} @ W_hh^T --------
    if (!first) {
        for (int kt = 0; kt < 32; ++kt) {
            const int k0 = kt * 16;
            float4 av = *reinterpret_cast<const float4*>(hprev_base + (size_t)am * HD + k0 + aq);
            float4 bv[3];
            #pragma unroll
            for (int i = 0; i < 3; ++i) {
                int idx = tid + 256 * i;
                int row = idx >> 2; int bq = (idx & 3) * 4;
                int grow = (row >> 6) * HD + j0 + (row & 63);
                bv[i] = *reinterpret_cast<const float4*>(w_hh + (size_t)grow * HD + k0 + bq);
            }
            __syncthreads();
            As[aq + 0][am] = av.x; As[aq + 1][am] = av.y; As[aq + 2][am] = av.z; As[aq + 3][am] = av.w;
            #pragma unroll
            for (int i = 0; i < 3; ++i) {
                int idx = tid + 256 * i;
                int row = idx >> 2; int bq = (idx & 3) * 4;
                Bs[bq + 0][row] = bv[i].x; Bs[bq + 1][row] = bv[i].y;
                Bs[bq + 2][row] = bv[i].z; Bs[bq + 3][row] = bv[i].w;
            }
            __syncthreads();
            #pragma unroll
            for (int k = 0; k < 16; ++k) {
                float4 a0 = *reinterpret_cast<const float4*>(&As[k][m0]);
                float4 a1 = *reinterpret_cast<const float4*>(&As[k][m0 + 4]);
                u64 aa[8];
                aa[0] = pack2(a0.x); aa[1] = pack2(a0.y); aa[2] = pack2(a0.z); aa[3] = pack2(a0.w);
                aa[4] = pack2(a1.x); aa[5] = pack2(a1.y); aa[6] = pack2(a1.z); aa[7] = pack2(a1.w);
                u64 b0 = *reinterpret_cast<const u64*>(&Bs[k][      (txn << 1)]);
                u64 b1 = *reinterpret_cast<const u64*>(&Bs[k][ 64 + (txn << 1)]);
                u64 b2 = *reinterpret_cast<const u64*>(&Bs[k][128 + (txn << 1)]);
                #pragma unroll
                for (int m = 0; m < 8; ++m) {
                    fma2(accR[m], aa[m], b0);
                    fma2(accZ[m], aa[m], b1);
                    fma2(accHN[m], aa[m], b2);
                }
            }
        }
    }

    // -------- x-phase: K = 160 over x_t @ W_ih^T --------
    for (int kt = 0; kt < 10; ++kt) {
        const int k0 = kt * 16;
        float4 av;
        {
            int kp = k0 + aq;
            if (kp < OBS)
                av = *reinterpret_cast<const float4*>(obs + (xrow + am) * OBS + kp);
            else
                av = *reinterpret_cast<const float4*>(act + (xrow + am) * ACTD + (kp - OBS));
        }
        float4 bv[3];
        #pragma unroll
        for (int i = 0; i < 3; ++i) {
            int idx = tid + 256 * i;
            int row = idx >> 2; int bq = (idx & 3) * 4;
            int grow = (row >> 6) * HD + j0 + (row & 63);
            bv[i] = *reinterpret_cast<const float4*>(w_ih + (size_t)grow * IND + k0 + bq);
        }
        __syncthreads();
        As[aq + 0][am] = av.x; As[aq + 1][am] = av.y; As[aq + 2][am] = av.z; As[aq + 3][am] = av.w;
        #pragma unroll
        for (int i = 0; i < 3; ++i) {
            int idx = tid + 256 * i;
            int row = idx >> 2; int bq = (idx & 3) * 4;
            Bs[bq + 0][row] = bv[i].x; Bs[bq + 1][row] = bv[i].y;
            Bs[bq + 2][row] = bv[i].z; Bs[bq + 3][row] = bv[i].w;
        }
        __syncthreads();
        #pragma unroll
        for (int k = 0; k < 16; ++k) {
            float4 a0 = *reinterpret_cast<const float4*>(&As[k][m0]);
            float4 a1 = *reinterpret_cast<const float4*>(&As[k][m0 + 4]);
            u64 aa[8];
            aa[0] = pack2(a0.x); aa[1] = pack2(a0.y); aa[2] = pack2(a0.z); aa[3] = pack2(a0.w);
            aa[4] = pack2(a1.x); aa[5] = pack2(a1.y); aa[6] = pack2(a1.z); aa[7] = pack2(a1.w);
            u64 b0 = *reinterpret_cast<const u64*>(&Bs[k][      (txn << 1)]);
            u64 b1 = *reinterpret_cast<const u64*>(&Bs[k][ 64 + (txn << 1)]);
            u64 b2 = *reinterpret_cast<const u64*>(&Bs[k][128 + (txn << 1)]);
            #pragma unroll
            for (int m = 0; m < 8; ++m) {
                fma2(accR[m], aa[m], b0);
                fma2(accZ[m], aa[m], b1);
                fma2(accIN[m], aa[m], b2);
            }
        }
    }

    // -------- epilogue: gates + state update, write h_t --------
    const size_t orow0 = ((size_t)(b * HOR + t) * Nq) * HD;
    const int jl = txn << 1;
    #pragma unroll
    for (int m = 0; m < 8; ++m) {
        const int n = m0 + m;
        float2 r2  = unpack2(accR[m]);
        float2 z2  = unpack2(accZ[m]);
        float2 hn2 = unpack2(accHN[m]);
        float2 in2 = unpack2(accIN[m]);
        float hp0 = 0.0f, hp1 = 0.0f;
        if (!first) {
            float2 hp = *reinterpret_cast<const float2*>(hprev_base + (size_t)n * HD + j0 + jl);
            hp0 = hp.x; hp1 = hp.y;
        }
        float r0 = sigmoidf_(r2.x + bih_s[jl]       + bhh_s[jl]);
        float z0 = sigmoidf_(z2.x + bih_s[64 + jl]  + bhh_s[64 + jl]);
        float n0 = tanhf(in2.x + bih_s[128 + jl] + r0 * (hn2.x + bhh_s[128 + jl]));
        float h0 = (1.0f - z0) * n0 + z0 * hp0;

        float r1 = sigmoidf_(r2.y + bih_s[jl + 1]   + bhh_s[jl + 1]);
        float z1 = sigmoidf_(z2.y + bih_s[65 + jl]  + bhh_s[65 + jl]);
        float n1 = tanhf(in2.y + bih_s[129 + jl] + r1 * (hn2.y + bhh_s[129 + jl]));
        float h1 = (1.0f - z1) * n1 + z1 * hp1;

        *reinterpret_cast<float2*>(hs + orow0 + (size_t)n * HD + j0 + jl) = make_float2(h0, h1);
    }
}

// ============================================================================
// Decode kernel: preds = hs @ w_dec^T + b_dec, one GEMM over all (t, bn) rows.
// M = HOR*2048, N = 128, K = 512. Tile BM=64 (one (b,t)), BN=128, BK=16.
// ============================================================================
__global__ __launch_bounds__(256, 2)
void dec_kernel(const float* __restrict__ hs, const float* __restrict__ w_dec,
                const float* __restrict__ b_dec, float* __restrict__ preds, int HOR)
{
    const int tid = threadIdx.x;
    const int mt  = blockIdx.x;     // 0 .. 32*HOR-1
    const int b   = mt & 31;
    const int t   = mt >> 5;
    const int tym = tid >> 5, txn = tid & 31;
    const int m0  = tym * 8;

    __shared__ float As[16][68];
    __shared__ float Bs[16][130];
    __shared__ float bdec_s[128];
    if (tid < 128) bdec_s[tid] = b_dec[tid];

    u64 acc0[8], acc1[8];
    #pragma unroll
    for (int m = 0; m < 8; ++m) { acc0[m] = 0; acc1[m] = 0; }

    const float* __restrict__ arow = hs + ((size_t)(b * HOR + t) * Nq) * HD;
    const int am = tid >> 2, aq = (tid & 3) * 4;

    for (int kt = 0; kt < 32; ++kt) {
        const int k0 = kt * 16;
        float4 av = *reinterpret_cast<const float4*>(arow + (size_t)am * HD + k0 + aq);
        float4 bv[2];
        #pragma unroll
        for (int i = 0; i < 2; ++i) {
            int idx = tid + 256 * i;          // < 512
            int row = idx >> 2; int bq = (idx & 3) * 4;
            bv[i] = *reinterpret_cast<const float4*>(w_dec + (size_t)row * HD + k0 + bq);
        }
        __syncthreads();
        As[aq + 0][am] = av.x; As[aq + 1][am] = av.y; As[aq + 2][am] = av.z; As[aq + 3][am] = av.w;
        #pragma unroll
        for (int i = 0; i < 2; ++i) {
            int idx = tid + 256 * i;
            int row = idx >> 2; int bq = (idx & 3) * 4;
            Bs[bq + 0][row] = bv[i].x; Bs[bq + 1][row] = bv[i].y;
            Bs[bq + 2][row] = bv[i].z; Bs[bq + 3][row] = bv[i].w;
        }
        __syncthreads();
        #pragma unroll
        for (int k = 0; k < 16; ++k) {
            float4 a0 = *reinterpret_cast<const float4*>(&As[k][m0]);
            float4 a1 = *reinterpret_cast<const float4*>(&As[k][m0 + 4]);
            u64 aa[8];
            aa[0] = pack2(a0.x); aa[1] = pack2(a0.y); aa[2] = pack2(a0.z); aa[3] = pack2(a0.w);
            aa[4] = pack2(a1.x); aa[5] = pack2(a1.y); aa[6] = pack2(a1.z); aa[7] = pack2(a1.w);
            u64 b0 = *reinterpret_cast<const u64*>(&Bs[k][     (txn << 1)]);
            u64 b1 = *reinterpret_cast<const u64*>(&Bs[k][64 + (txn << 1)]);
            #pragma unroll
            for (int m = 0; m < 8; ++m) {
                fma2(acc0[m], aa[m], b0);
                fma2(acc1[m], aa[m], b1);
            }
        }
    }

    const size_t prow0 = ((size_t)(b * HOR + t) * Nq) * DD;
    const int jl = txn << 1;
    #pragma unroll
    for (int m = 0; m < 8; ++m) {
        const int n = m0 + m;
        float2 v0 = unpack2(acc0[m]);
        float2 v1 = unpack2(acc1[m]);
        *reinterpret_cast<float2*>(preds + prow0 + (size_t)n * DD + jl) =
            make_float2(v0.x + bdec_s[jl], v0.y + bdec_s[jl + 1]);
        *reinterpret_cast<float2*>(preds + prow0 + (size_t)n * DD + 64 + jl) =
            make_float2(v1.x + bdec_s[64 + jl], v1.y + bdec_s[65 + jl]);
    }
}

// ============================================================================
// Launch: 63 sequential step kernels (recurrence), then one decode GEMM.
// horizon derived from out_size (out = preds[B,HOR,N,128] ++ hs[B,HOR,N,512]).
// ============================================================================
extern "C" void kernel_launch(void* const* d_in, const int* in_sizes, int n_in,
                              void* d_out, int out_size)
{
    const float* obs   = (const float*)d_in[0];
    const float* act   = (const float*)d_in[1];
    const float* w_ih  = (const float*)d_in[2];
    const float* w_hh  = (const float*)d_in[3];
    const float* b_ih  = (const float*)d_in[4];
    const float* b_hh  = (const float*)d_in[5];
    const float* w_dec = (const float*)d_in[6];
    const float* b_dec = (const float*)d_in[7];
    // d_in[8] is `horizon` (device int); value recovered from out_size instead
    // so launch shapes stay host-side and graph-capturable.

    const int T   = in_sizes[0] / (Bq * Nq * OBS);          // 64
    const int HOR = out_size / (Bq * Nq * (DD + HD));       // 63

    float* preds = (float*)d_out;
    float* hs    = preds + (size_t)Bq * HOR * Nq * DD;

    dim3 sgrid(Bq, HD / 64);
    for (int t = 0; t < HOR; ++t) {
        gru_step_kernel<<<sgrid, 256>>>(obs, act, w_ih, w_hh, b_ih, b_hh, hs, t, HOR, T);
    }
    dec_kernel<<<Bq * HOR, 256>>>(hs, w_dec, b_dec, preds, HOR);
}

// round 4
// speedup vs baseline: 1.0005x; 1.0005x over previous
#include <cuda_runtime.h>
#include <cstdint>
#include <math.h>

// Problem constants (GRUWorldModel): OBS=128, ACT=32, H=512, B=32, N=64
#define Bq   32
#define Nq   64
#define HD   512
#define OBS  128
#define ACTD 32
#define IND  160
#define DD   128

typedef unsigned long long u64;

// ---- packed f32x2 helpers (sm_100+) ----
__device__ __forceinline__ u64 pack2(float x) {
    u64 r; asm("mov.b64 %0, {%1,%2};" : "=l"(r) : "f"(x), "f"(x)); return r;
}
__device__ __forceinline__ void fma2(u64 &d, u64 a, u64 b) {
    asm("fma.rn.f32x2 %0, %1, %2, %0;" : "+l"(d) : "l"(a), "l"(b));
}
__device__ __forceinline__ float2 unpack2(u64 v) {
    float2 f; asm("mov.b64 {%0,%1}, %2;" : "=f"(f.x), "=f"(f.y) : "l"(v)); return f;
}
__device__ __forceinline__ float sigmoidf_(float x) { return 1.0f / (1.0f + expf(-x)); }

// ============================================================================
// Per-timestep kernel: fused GEMM ( [x_t, h_{t-1}] @ [W_ih | W_hh]^T ) + gates.
// Grid: (32 b-tiles, 8 j-groups of 64). Block 256 threads.
// Tile: BM=64 rows (one b, n=0..63), BN=192 cols = {r,z,n} gate rows at the
// same j-slice, BK=16. Each thread: 8 rows x 6 cols as 8x3 f32x2 accumulators.
// Separate accumulators for the x-part and h-part of the n gate.
// h_t is written directly into the hs region of d_out; h_{t-1} is read there.
// ============================================================================
__global__ __launch_bounds__(256, 2)
void gru_step_kernel(const float* __restrict__ obs, const float* __restrict__ act,
                     const float* __restrict__ w_ih, const float* __restrict__ w_hh,
                     const float* __restrict__ b_ih, const float* __restrict__ b_hh,
                     float* __restrict__ hs, int t, int HOR, int T)
{
    const int tid = threadIdx.x;
    const int b   = blockIdx.x;        // 0..31
    const int j0  = blockIdx.y * 64;   // 0..448
    const int tym = tid >> 5;          // warp id 0..7
    const int txn = tid & 31;
    const int m0  = tym * 8;

    __shared__ float As[16][68];       // A tile transposed: As[k][m]
    __shared__ float Bs[16][194];      // B tile transposed: Bs[k][col], col<192
    __shared__ float bih_s[192];
    __shared__ float bhh_s[192];

    if (tid < 192) {
        int grow = (tid >> 6) * HD + j0 + (tid & 63);
        bih_s[tid] = b_ih[grow];
        bhh_s[tid] = b_hh[grow];
    }

    u64 accR[8], accZ[8], accHN[8], accIN[8];
    #pragma unroll
    for (int m = 0; m < 8; ++m) { accR[m] = 0; accZ[m] = 0; accHN[m] = 0; accIN[m] = 0; }

    const int am = tid >> 2;            // A-load row 0..63
    const int aq = (tid & 3) * 4;       // A-load k offset 0,4,8,12

    const bool first = (t == 0);
    const float* __restrict__ hprev_base =
        hs + ((size_t)(b * HOR + (t - 1)) * Nq) * HD;   // only deref'd if !first
    const size_t xrow = ((size_t)(b * T + t)) * Nq;

    // -------- h-phase: K = 512 over h_{t-1} @ W_hh^T --------
    if (!first) {
        for (int kt = 0; kt < 32; ++kt) {
            const int k0 = kt * 16;
            float4 av = *reinterpret_cast<const float4*>(hprev_base + (size_t)am * HD + k0 + aq);
            float4 bv[3];
            #pragma unroll
            for (int i = 0; i < 3; ++i) {
                int idx = tid + 256 * i;
                int row = idx >> 2; int bq = (idx & 3) * 4;
                int grow = (row >> 6) * HD + j0 + (row & 63);
                bv[i] = *reinterpret_cast<const float4*>(w_hh + (size_t)grow * HD + k0 + bq);
            }
            __syncthreads();
            As[aq + 0][am] = av.x; As[aq + 1][am] = av.y; As[aq + 2][am] = av.z; As[aq + 3][am] = av.w;
            #pragma unroll
            for (int i = 0; i < 3; ++i) {
                int idx = tid + 256 * i;
                int row = idx >> 2; int bq = (idx & 3) * 4;
                Bs[bq + 0][row] = bv[i].x; Bs[bq + 1][row] = bv[i].y;
                Bs[bq + 2][row] = bv[i].z; Bs[bq + 3][row] = bv[i].w;
            }
            __syncthreads();
            #pragma unroll
            for (int k = 0; k < 16; ++k) {
                float4 a0 = *reinterpret_cast<const float4*>(&As[k][m0]);
                float4 a1 = *reinterpret_cast<const float4*>(&As[k][m0 + 4]);
                u64 aa[8];
                aa[0] = pack2(a0.x); aa[1] = pack2(a0.y); aa[2] = pack2(a0.z); aa[3] = pack2(a0.w);
                aa[4] = pack2(a1.x); aa[5] = pack2(a1.y); aa[6] = pack2(a1.z); aa[7] = pack2(a1.w);
                u64 b0 = *reinterpret_cast<const u64*>(&Bs[k][      (txn << 1)]);
                u64 b1 = *reinterpret_cast<const u64*>(&Bs[k][ 64 + (txn << 1)]);
                u64 b2 = *reinterpret_cast<const u64*>(&Bs[k][128 + (txn << 1)]);
                #pragma unroll
                for (int m = 0; m < 8; ++m) {
                    fma2(accR[m], aa[m], b0);
                    fma2(accZ[m], aa[m], b1);
                    fma2(accHN[m], aa[m], b2);
                }
            }
        }
    }

    // -------- x-phase: K = 160 over x_t @ W_ih^T --------
    for (int kt = 0; kt < 10; ++kt) {
        const int k0 = kt * 16;
        float4 av;
        {
            int kp = k0 + aq;
            if (kp < OBS)
                av = *reinterpret_cast<const float4*>(obs + (xrow + am) * OBS + kp);
            else
                av = *reinterpret_cast<const float4*>(act + (xrow + am) * ACTD + (kp - OBS));
        }
        float4 bv[3];
        #pragma unroll
        for (int i = 0; i < 3; ++i) {
            int idx = tid + 256 * i;
            int row = idx >> 2; int bq = (idx & 3) * 4;
            int grow = (row >> 6) * HD + j0 + (row & 63);
            bv[i] = *reinterpret_cast<const float4*>(w_ih + (size_t)grow * IND + k0 + bq);
        }
        __syncthreads();
        As[aq + 0][am] = av.x; As[aq + 1][am] = av.y; As[aq + 2][am] = av.z; As[aq + 3][am] = av.w;
        #pragma unroll
        for (int i = 0; i < 3; ++i) {
            int idx = tid + 256 * i;
            int row = idx >> 2; int bq = (idx & 3) * 4;
            Bs[bq + 0][row] = bv[i].x; Bs[bq + 1][row] = bv[i].y;
            Bs[bq + 2][row] = bv[i].z; Bs[bq + 3][row] = bv[i].w;
        }
        __syncthreads();
        #pragma unroll
        for (int k = 0; k < 16; ++k) {
            float4 a0 = *reinterpret_cast<const float4*>(&As[k][m0]);
            float4 a1 = *reinterpret_cast<const float4*>(&As[k][m0 + 4]);
            u64 aa[8];
            aa[0] = pack2(a0.x); aa[1] = pack2(a0.y); aa[2] = pack2(a0.z); aa[3] = pack2(a0.w);
            aa[4] = pack2(a1.x); aa[5] = pack2(a1.y); aa[6] = pack2(a1.z); aa[7] = pack2(a1.w);
            u64 b0 = *reinterpret_cast<const u64*>(&Bs[k][      (txn << 1)]);
            u64 b1 = *reinterpret_cast<const u64*>(&Bs[k][ 64 + (txn << 1)]);
            u64 b2 = *reinterpret_cast<const u64*>(&Bs[k][128 + (txn << 1)]);
            #pragma unroll
            for (int m = 0; m < 8; ++m) {
                fma2(accR[m], aa[m], b0);
                fma2(accZ[m], aa[m], b1);
                fma2(accIN[m], aa[m], b2);
            }
        }
    }

    // -------- epilogue: gates + state update, write h_t --------
    const size_t orow0 = ((size_t)(b * HOR + t) * Nq) * HD;
    const int jl = txn << 1;
    #pragma unroll
    for (int m = 0; m < 8; ++m) {
        const int n = m0 + m;
        float2 r2  = unpack2(accR[m]);
        float2 z2  = unpack2(accZ[m]);
        float2 hn2 = unpack2(accHN[m]);
        float2 in2 = unpack2(accIN[m]);
        float hp0 = 0.0f, hp1 = 0.0f;
        if (!first) {
            float2 hp = *reinterpret_cast<const float2*>(hprev_base + (size_t)n * HD + j0 + jl);
            hp0 = hp.x; hp1 = hp.y;
        }
        float r0 = sigmoidf_(r2.x + bih_s[jl]       + bhh_s[jl]);
        float z0 = sigmoidf_(z2.x + bih_s[64 + jl]  + bhh_s[64 + jl]);
        float n0 = tanhf(in2.x + bih_s[128 + jl] + r0 * (hn2.x + bhh_s[128 + jl]));
        float h0 = (1.0f - z0) * n0 + z0 * hp0;

        float r1 = sigmoidf_(r2.y + bih_s[jl + 1]   + bhh_s[jl + 1]);
        float z1 = sigmoidf_(z2.y + bih_s[65 + jl]  + bhh_s[65 + jl]);
        float n1 = tanhf(in2.y + bih_s[129 + jl] + r1 * (hn2.y + bhh_s[129 + jl]));
        float h1 = (1.0f - z1) * n1 + z1 * hp1;

        *reinterpret_cast<float2*>(hs + orow0 + (size_t)n * HD + j0 + jl) = make_float2(h0, h1);
    }
}

// ============================================================================
// Decode kernel: preds = hs @ w_dec^T + b_dec, one GEMM over all (t, bn) rows.
// M = HOR*2048, N = 128, K = 512. Tile BM=64 (one (b,t)), BN=128, BK=16.
// ============================================================================
__global__ __launch_bounds__(256, 2)
void dec_kernel(const float* __restrict__ hs, const float* __restrict__ w_dec,
                const float* __restrict__ b_dec, float* __restrict__ preds, int HOR)
{
    const int tid = threadIdx.x;
    const int mt  = blockIdx.x;     // 0 .. 32*HOR-1
    const int b   = mt & 31;
    const int t   = mt >> 5;
    const int tym = tid >> 5, txn = tid & 31;
    const int m0  = tym * 8;

    __shared__ float As[16][68];
    __shared__ float Bs[16][130];
    __shared__ float bdec_s[128];
    if (tid < 128) bdec_s[tid] = b_dec[tid];

    u64 acc0[8], acc1[8];
    #pragma unroll
    for (int m = 0; m < 8; ++m) { acc0[m] = 0; acc1[m] = 0; }

    const float* __restrict__ arow = hs + ((size_t)(b * HOR + t) * Nq) * HD;
    const int am = tid >> 2, aq = (tid & 3) * 4;

    for (int kt = 0; kt < 32; ++kt) {
        const int k0 = kt * 16;
        float4 av = *reinterpret_cast<const float4*>(arow + (size_t)am * HD + k0 + aq);
        float4 bv[2];
        #pragma unroll
        for (int i = 0; i < 2; ++i) {
            int idx = tid + 256 * i;          // < 512
            int row = idx >> 2; int bq = (idx & 3) * 4;
            bv[i] = *reinterpret_cast<const float4*>(w_dec + (size_t)row * HD + k0 + bq);
        }
        __syncthreads();
        As[aq + 0][am] = av.x; As[aq + 1][am] = av.y; As[aq + 2][am] = av.z; As[aq + 3][am] = av.w;
        #pragma unroll
        for (int i = 0; i < 2; ++i) {
            int idx = tid + 256 * i;
            int row = idx >> 2; int bq = (idx & 3) * 4;
            Bs[bq + 0][row] = bv[i].x; Bs[bq + 1][row] = bv[i].y;
            Bs[bq + 2][row] = bv[i].z; Bs[bq + 3][row] = bv[i].w;
        }
        __syncthreads();
        #pragma unroll
        for (int k = 0; k < 16; ++k) {
            float4 a0 = *reinterpret_cast<const float4*>(&As[k][m0]);
            float4 a1 = *reinterpret_cast<const float4*>(&As[k][m0 + 4]);
            u64 aa[8];
            aa[0] = pack2(a0.x); aa[1] = pack2(a0.y); aa[2] = pack2(a0.z); aa[3] = pack2(a0.w);
            aa[4] = pack2(a1.x); aa[5] = pack2(a1.y); aa[6] = pack2(a1.z); aa[7] = pack2(a1.w);
            u64 b0 = *reinterpret_cast<const u64*>(&Bs[k][     (txn << 1)]);
            u64 b1 = *reinterpret_cast<const u64*>(&Bs[k][64 + (txn << 1)]);
            #pragma unroll
            for (int m = 0; m < 8; ++m) {
                fma2(acc0[m], aa[m], b0);
                fma2(acc1[m], aa[m], b1);
            }
        }
    }

    const size_t prow0 = ((size_t)(b * HOR + t) * Nq) * DD;
    const int jl = txn << 1;
    #pragma unroll
    for (int m = 0; m < 8; ++m) {
        const int n = m0 + m;
        float2 v0 = unpack2(acc0[m]);
        float2 v1 = unpack2(acc1[m]);
        *reinterpret_cast<float2*>(preds + prow0 + (size_t)n * DD + jl) =
            make_float2(v0.x + bdec_s[jl], v0.y + bdec_s[jl + 1]);
        *reinterpret_cast<float2*>(preds + prow0 + (size_t)n * DD + 64 + jl) =
            make_float2(v1.x + bdec_s[64 + jl], v1.y + bdec_s[65 + jl]);
    }
}

// ============================================================================
// Launch: 63 sequential step kernels (recurrence), then one decode GEMM.
// horizon derived from out_size (out = preds[B,HOR,N,128] ++ hs[B,HOR,N,512]).
// ============================================================================
extern "C" void kernel_launch(void* const* d_in, const int* in_sizes, int n_in,
                              void* d_out, int out_size)
{
    const float* obs   = (const float*)d_in[0];
    const float* act   = (const float*)d_in[1];
    const float* w_ih  = (const float*)d_in[2];
    const float* w_hh  = (const float*)d_in[3];
    const float* b_ih  = (const float*)d_in[4];
    const float* b_hh  = (const float*)d_in[5];
    const float* w_dec = (const float*)d_in[6];
    const float* b_dec = (const float*)d_in[7];
    // d_in[8] is `horizon` (device int); value recovered from out_size instead
    // so launch shapes stay host-side and graph-capturable.

    const int T   = in_sizes[0] / (Bq * Nq * OBS);          // 64
    const int HOR = out_size / (Bq * Nq * (DD + HD));       // 63

    float* preds = (float*)d_out;
    float* hs    = preds + (size_t)Bq * HOR * Nq * DD;

    dim3 sgrid(Bq, HD / 64);
    for (int t = 0; t < HOR; ++t) {
        gru_step_kernel<<<sgrid, 256>>>(obs, act, w_ih, w_hh, b_ih, b_hh, hs, t, HOR, T);
    }
    dec_kernel<<<Bq * HOR, 256>>>(hs, w_dec, b_dec, preds, HOR);
}